// round 1
// baseline (speedup 1.0000x reference)
#include <cuda_runtime.h>
#include <math.h>

#define NN 5000
#define EE 40000

// ---------------- scratch (device globals: no allocations allowed) ----------
__device__ float g_sh1[EE * 3];   // sqrt3 * (ny, nz, nx)
__device__ float g_hly[EE * 8];   // hidden activations of ly MLP
__device__ float g_het[EE * 8];   // hidden activations of et MLP
__device__ float g_s [NN * 32];   // stage-1 node scalars (accum then mean)
__device__ float g_v [NN * 96];   // stage-1 node vectors [u*3+i]
__device__ float g_cs[NN * 32];   // layer conv scalar accum
__device__ float g_cv[NN * 96];   // layer conv vector accum
__device__ float g_s2[NN * 32];   // final node scalars
__device__ float g_v2[NN * 96];   // final node vectors
__device__ float g_cnt[NN];       // in-degree
__device__ float g_A1[100 * 9 * 32]; // per-type: sum_u emb[t,u]*ipW1[k, u*32+w] (+bias row k=8)
__device__ float g_A2[100 * 9 * 32]; // same for the 1o path (offset 1024)

#define FULLMASK 0xffffffffu
__device__ __forceinline__ float siluf(float x) { return x / (1.f + __expf(-x)); }

constexpr float SQRT3      = 1.7320508075688772f;
constexpr float INV_SQRT3  = 0.57735026918962576f;
constexpr float C_IP       = 0.17677669529663687f;  // 1/sqrt(32)
constexpr float C_LY       = 0.125f;                // 1/sqrt(64)
constexpr float C_ET       = 0.08838834764831843f;  // 1/sqrt(128)
constexpr float LC         = 0.17677669529663687f;  // o3.Linear norm 1/sqrt(32)
constexpr float INV_SQRT32 = 0.17677669529663687f;
constexpr float INV_SQRT13 = 0.27735009811261457f;
constexpr float CUTOFF     = 5.0f;

// ---------------- kernels ----------------------------------------------------

__global__ void k_zero(int N) {
    int tid = blockIdx.x * blockDim.x + threadIdx.x;
    int stride = gridDim.x * blockDim.x;
    for (int i = tid; i < N * 32; i += stride) { g_s[i] = 0.f; g_cs[i] = 0.f; }
    for (int i = tid; i < N * 96; i += stride) { g_v[i] = 0.f; g_cv[i] = 0.f; }
    for (int i = tid; i < N;      i += stride) g_cnt[i] = 0.f;
}

// per-atom-type contraction of atom_embed with ip_W1 / ip_b1
__global__ void k_pretype(const float* __restrict__ emb,
                          const float* __restrict__ ipW1,
                          const float* __restrict__ ipb1) {
    int t = blockIdx.x;        // 0..99
    int w = threadIdx.x;       // 0..31
    float e[32];
#pragma unroll
    for (int u = 0; u < 32; u++) e[u] = emb[t * 32 + u];
    for (int k = 0; k < 8; k++) {
        float a1 = 0.f, a2 = 0.f;
#pragma unroll
        for (int u = 0; u < 32; u++) {
            a1 += e[u] * ipW1[k * 2048 +        u * 32 + w];
            a2 += e[u] * ipW1[k * 2048 + 1024 + u * 32 + w];
        }
        g_A1[t * 288 + k * 32 + w] = a1;
        g_A2[t * 288 + k * 32 + w] = a2;
    }
    float b1 = 0.f, b2 = 0.f;
#pragma unroll
    for (int u = 0; u < 32; u++) {
        b1 += e[u] * ipb1[       u * 32 + w];
        b2 += e[u] * ipb1[1024 + u * 32 + w];
    }
    g_A1[t * 288 + 8 * 32 + w] = b1;
    g_A2[t * 288 + 8 * 32 + w] = b2;
}

// per-edge geometry + 3 radial-MLP hiddens + stage-1 message & scatter
__global__ void k_edge1(const float* __restrict__ coords,
                        const int*   __restrict__ atom_types,
                        const int*   __restrict__ ei,
                        const float* __restrict__ ipW0, const float* __restrict__ ipb0,
                        const float* __restrict__ lyW0, const float* __restrict__ lyb0,
                        const float* __restrict__ etW0, const float* __restrict__ etb0,
                        int E) {
    int lane = threadIdx.x & 31;
    int e = blockIdx.x * (blockDim.x >> 5) + (threadIdx.x >> 5);
    if (e >= E) return;
    int src = ei[e], dst = ei[E + e];

    float dx = coords[dst * 3 + 0] - coords[src * 3 + 0];
    float dy = coords[dst * 3 + 1] - coords[src * 3 + 1];
    float dz = coords[dst * 3 + 2] - coords[src * 3 + 2];
    float d  = sqrtf(dx * dx + dy * dy + dz * dz + 1e-12f);
    float inv_d = 1.f / d;
    float nx = dx * inv_d, ny = dy * inv_d, nz = dz * inv_d;
    float sh_0 = SQRT3 * ny, sh_1 = SQRT3 * nz, sh_2 = SQRT3 * nx;

    // gaussian radial basis
    float attr[8];
    constexpr float STEP = CUTOFF / 9.0f;
    constexpr float INV_STEP = 9.0f / CUTOFF;
#pragma unroll
    for (int i = 0; i < 8; i++) {
        float diff = (d - (float)(i + 1) * STEP) * INV_STEP;
        attr[i] = __expf(-diff * diff) * (1.0f / 1.12f);
    }

    // lanes 0..7 -> ip hidden, 8..15 -> ly hidden, 16..23 -> et hidden
    int grp = lane >> 3;
    int j   = lane & 7;
    const float* W0 = (grp == 1) ? lyW0 : (grp == 2) ? etW0 : ipW0;
    const float* b0 = (grp == 1) ? lyb0 : (grp == 2) ? etb0 : ipb0;
    float pre = b0[j];
#pragma unroll
    for (int i = 0; i < 8; i++) pre += attr[i] * W0[i * 8 + j];
    float myh = siluf(pre);

    if (grp == 1) g_hly[e * 8 + j] = myh;
    if (grp == 2) g_het[e * 8 + j] = myh;
    if (lane < 3) g_sh1[e * 3 + lane] = (lane == 0) ? sh_0 : (lane == 1) ? sh_1 : sh_2;

    // stage-1 message via per-type precomputed matrices
    int t = atom_types[src];
    const float* A1 = &g_A1[t * 288];
    const float* A2 = &g_A2[t * 288];
    float m1 = A1[8 * 32 + lane];
    float m2 = A2[8 * 32 + lane];
#pragma unroll
    for (int k = 0; k < 8; k++) {
        float hk = __shfl_sync(FULLMASK, myh, k);  // lanes 0..7 hold ip hidden
        m1 += hk * A1[k * 32 + lane];
        m2 += hk * A2[k * 32 + lane];
    }
    atomicAdd(&g_s[dst * 32 + lane], C_IP * m1);
    float cm2 = C_IP * m2;
    atomicAdd(&g_v[dst * 96 + lane * 3 + 0], cm2 * sh_0);
    atomicAdd(&g_v[dst * 96 + lane * 3 + 1], cm2 * sh_1);
    atomicAdd(&g_v[dst * 96 + lane * 3 + 2], cm2 * sh_2);
    if (lane == 0) atomicAdd(&g_cnt[dst], 1.f);
}

// divide stage-1 accumulators by count (scatter mean)
__global__ void k_norm1(int N) {
    int idx = blockIdx.x * blockDim.x + threadIdx.x;
    if (idx >= N * 32) return;
    int n = idx >> 5;
    float c = g_cnt[n];
    float inv = 1.f / fmaxf(c, 1.f);
    g_s[idx] *= inv;
    int u = idx & 31;
    g_v[n * 96 + u * 3 + 0] *= inv;
    g_v[n * 96 + u * 3 + 1] *= inv;
    g_v[n * 96 + u * 3 + 2] *= inv;
}

// heavy layer: FCTP(32x0e+32x1o, sh) with per-edge generated 4x32x32 weights
__global__ void __launch_bounds__(256, 1)
k_ly(const float* __restrict__ W1, const float* __restrict__ B1,
     const int* __restrict__ ei, int E) {
    extern __shared__ float sm[];
    float* sW = sm;            // 8 * 4096
    float* sB = sm + 32768;    // 4096
    for (int i = threadIdx.x; i < 32768; i += blockDim.x) sW[i] = W1[i];
    for (int i = threadIdx.x; i < 4096;  i += blockDim.x) sB[i] = B1[i];
    __syncthreads();

    int lane  = threadIdx.x & 31;
    int warp  = blockIdx.x * (blockDim.x >> 5) + (threadIdx.x >> 5);
    int nwarp = gridDim.x * (blockDim.x >> 5);

    for (int e = warp; e < E; e += nwarp) {
        int src = ei[e], dst = ei[E + e];
        float sh_0 = g_sh1[e * 3 + 0], sh_1 = g_sh1[e * 3 + 1], sh_2 = g_sh1[e * 3 + 2];
        const float4* hp = reinterpret_cast<const float4*>(&g_hly[e * 8]);
        float4 ha = hp[0], hb = hp[1];
        float h0 = ha.x, h1 = ha.y, h2 = ha.z, h3 = ha.w;
        float h4 = hb.x, h5 = hb.y, h6 = hb.z, h7 = hb.w;

        float sl  = g_s[src * 32 + lane];
        float vl0 = g_v[src * 96 + lane * 3 + 0];
        float vl1 = g_v[src * 96 + lane * 3 + 1];
        float vl2 = g_v[src * 96 + lane * 3 + 2];
        float dl  = (vl0 * sh_0 + vl1 * sh_1 + vl2 * sh_2) * INV_SQRT3;

        float acc_s = 0.f, a1 = 0.f, av0 = 0.f, av1 = 0.f, av2 = 0.f;
#pragma unroll 4
        for (int u = 0; u < 32; u++) {
            float su  = __shfl_sync(FULLMASK, sl,  u);
            float du  = __shfl_sync(FULLMASK, dl,  u);
            float vu0 = __shfl_sync(FULLMASK, vl0, u);
            float vu1 = __shfl_sync(FULLMASK, vl1, u);
            float vu2 = __shfl_sync(FULLMASK, vl2, u);
            int b = u * 32 + lane;
            float w0 = sB[b], w1 = sB[1024 + b], w2 = sB[2048 + b], w3 = sB[3072 + b];
            w0 += h0 * sW[0 * 4096 + b]        + h1 * sW[1 * 4096 + b]
                + h2 * sW[2 * 4096 + b]        + h3 * sW[3 * 4096 + b]
                + h4 * sW[4 * 4096 + b]        + h5 * sW[5 * 4096 + b]
                + h6 * sW[6 * 4096 + b]        + h7 * sW[7 * 4096 + b];
            w1 += h0 * sW[0 * 4096 + 1024 + b] + h1 * sW[1 * 4096 + 1024 + b]
                + h2 * sW[2 * 4096 + 1024 + b] + h3 * sW[3 * 4096 + 1024 + b]
                + h4 * sW[4 * 4096 + 1024 + b] + h5 * sW[5 * 4096 + 1024 + b]
                + h6 * sW[6 * 4096 + 1024 + b] + h7 * sW[7 * 4096 + 1024 + b];
            w2 += h0 * sW[0 * 4096 + 2048 + b] + h1 * sW[1 * 4096 + 2048 + b]
                + h2 * sW[2 * 4096 + 2048 + b] + h3 * sW[3 * 4096 + 2048 + b]
                + h4 * sW[4 * 4096 + 2048 + b] + h5 * sW[5 * 4096 + 2048 + b]
                + h6 * sW[6 * 4096 + 2048 + b] + h7 * sW[7 * 4096 + 2048 + b];
            w3 += h0 * sW[0 * 4096 + 3072 + b] + h1 * sW[1 * 4096 + 3072 + b]
                + h2 * sW[2 * 4096 + 3072 + b] + h3 * sW[3 * 4096 + 3072 + b]
                + h4 * sW[4 * 4096 + 3072 + b] + h5 * sW[5 * 4096 + 3072 + b]
                + h6 * sW[6 * 4096 + 3072 + b] + h7 * sW[7 * 4096 + 3072 + b];
            acc_s += su * w0 + du * w3;
            a1    += su * w1;
            av0   += vu0 * w2;
            av1   += vu1 * w2;
            av2   += vu2 * w2;
        }
        atomicAdd(&g_cs[dst * 32 + lane],          C_LY * acc_s);
        atomicAdd(&g_cv[dst * 96 + lane * 3 + 0],  C_LY * (sh_0 * a1 + av0));
        atomicAdd(&g_cv[dst * 96 + lane * 3 + 1],  C_LY * (sh_1 * a1 + av1));
        atomicAdd(&g_cv[dst * 96 + lane * 3 + 2],  C_LY * (sh_2 * a1 + av2));
    }
}

// conv mean + linear self-interaction -> final node features
__global__ void k_norm2(const float* __restrict__ Ws, const float* __restrict__ Wv, int N) {
    int lane = threadIdx.x & 31;
    int n = blockIdx.x * (blockDim.x >> 5) + (threadIdx.x >> 5);
    if (n >= N) return;
    float inv = 1.f / fmaxf(g_cnt[n], 1.f);
    float sl  = g_s[n * 32 + lane];
    float vl0 = g_v[n * 96 + lane * 3 + 0];
    float vl1 = g_v[n * 96 + lane * 3 + 1];
    float vl2 = g_v[n * 96 + lane * 3 + 2];
    float ls = 0.f, lv0 = 0.f, lv1 = 0.f, lv2 = 0.f;
#pragma unroll 4
    for (int u = 0; u < 32; u++) {
        float su  = __shfl_sync(FULLMASK, sl,  u);
        float vu0 = __shfl_sync(FULLMASK, vl0, u);
        float vu1 = __shfl_sync(FULLMASK, vl1, u);
        float vu2 = __shfl_sync(FULLMASK, vl2, u);
        float ws = Ws[u * 32 + lane];
        float wv = Wv[u * 32 + lane];
        ls  += su  * ws;
        lv0 += vu0 * wv;
        lv1 += vu1 * wv;
        lv2 += vu2 * wv;
    }
    g_s2[n * 32 + lane]         = g_cs[n * 32 + lane] * inv         + LC * ls;
    g_v2[n * 96 + lane * 3 + 0] = g_cv[n * 96 + lane * 3 + 0] * inv + LC * lv0;
    g_v2[n * 96 + lane * 3 + 1] = g_cv[n * 96 + lane * 3 + 1] * inv + LC * lv1;
    g_v2[n * 96 + lane * 3 + 2] = g_cv[n * 96 + lane * 3 + 2] * inv + LC * lv2;
}

// edge output tensor product -> 5 bond logits per edge
__global__ void k_et(const float* __restrict__ W1, const float* __restrict__ B1,
                     const int* __restrict__ ei, float* __restrict__ out, int E) {
    __shared__ float sW[8 * 640];
    __shared__ float sB[640];
    for (int i = threadIdx.x; i < 8 * 640; i += blockDim.x) sW[i] = W1[i];
    for (int i = threadIdx.x; i < 640;     i += blockDim.x) sB[i] = B1[i];
    __syncthreads();

    int lane = threadIdx.x & 31;   // = u
    int e = blockIdx.x * (blockDim.x >> 5) + (threadIdx.x >> 5);
    if (e >= E) return;
    int src = ei[e], dst = ei[E + e];
    float sh_0 = g_sh1[e * 3 + 0], sh_1 = g_sh1[e * 3 + 1], sh_2 = g_sh1[e * 3 + 2];
    const float4* hp = reinterpret_cast<const float4*>(&g_het[e * 8]);
    float4 ha = hp[0], hb = hp[1];
    float h[8] = {ha.x, ha.y, ha.z, ha.w, hb.x, hb.y, hb.z, hb.w};

    float x[4];
    x[0] = g_s2[src * 32 + lane];
    {
        float a = g_v2[src * 96 + lane * 3 + 0];
        float b = g_v2[src * 96 + lane * 3 + 1];
        float c = g_v2[src * 96 + lane * 3 + 2];
        x[1] = (a * sh_0 + b * sh_1 + c * sh_2) * INV_SQRT3;
    }
    x[2] = g_s2[dst * 32 + lane];
    {
        float a = g_v2[dst * 96 + lane * 3 + 0];
        float b = g_v2[dst * 96 + lane * 3 + 1];
        float c = g_v2[dst * 96 + lane * 3 + 2];
        x[3] = (a * sh_0 + b * sh_1 + c * sh_2) * INV_SQRT3;
    }

    float p0 = 0.f, p1 = 0.f, p2 = 0.f, p3 = 0.f, p4 = 0.f;
#pragma unroll
    for (int P = 0; P < 4; P++) {
        int base = P * 160 + lane * 5;
        float xp = x[P];
#pragma unroll
        for (int w = 0; w < 5; w++) {
            float wt = sB[base + w];
#pragma unroll
            for (int k = 0; k < 8; k++) wt += h[k] * sW[k * 640 + base + w];
            float contrib = xp * wt;
            if (w == 0) p0 += contrib;
            else if (w == 1) p1 += contrib;
            else if (w == 2) p2 += contrib;
            else if (w == 3) p3 += contrib;
            else p4 += contrib;
        }
    }
#pragma unroll
    for (int off = 16; off > 0; off >>= 1) {
        p0 += __shfl_xor_sync(FULLMASK, p0, off);
        p1 += __shfl_xor_sync(FULLMASK, p1, off);
        p2 += __shfl_xor_sync(FULLMASK, p2, off);
        p3 += __shfl_xor_sync(FULLMASK, p3, off);
        p4 += __shfl_xor_sync(FULLMASK, p4, off);
    }
    if (lane == 0) {
        out[e * 5 + 0] = C_ET * p0;
        out[e * 5 + 1] = C_ET * p1;
        out[e * 5 + 2] = C_ET * p2;
        out[e * 5 + 3] = C_ET * p3;
        out[e * 5 + 4] = C_ET * p4;
    }
}

// node output MLP (13x0e)
__global__ void k_nodeout(const float* __restrict__ W1, const float* __restrict__ W2,
                          float* __restrict__ out, int N) {
    int n = blockIdx.x * blockDim.x + threadIdx.x;
    if (n >= N) return;
    float s[32];
#pragma unroll
    for (int u = 0; u < 32; u++) s[u] = g_s2[n * 32 + u];
    float h[13];
#pragma unroll
    for (int j = 0; j < 13; j++) {
        float pre = 0.f;
#pragma unroll
        for (int u = 0; u < 32; u++) pre += s[u] * W1[u * 13 + j];
        pre *= INV_SQRT32;
        h[j] = siluf(pre);
    }
#pragma unroll
    for (int j2 = 0; j2 < 13; j2++) {
        float o = 0.f;
#pragma unroll
        for (int j = 0; j < 13; j++) o += h[j] * W2[j * 13 + j2];
        out[n * 13 + j2] = o * INV_SQRT13;
    }
}

// ---------------- launch ------------------------------------------------------

extern "C" void kernel_launch(void* const* d_in, const int* in_sizes, int n_in,
                              void* d_out, int out_size) {
    const float* coords     = (const float*)d_in[0];
    const int*   atom_types = (const int*)  d_in[1];
    const int*   ei         = (const int*)  d_in[2];
    const float* atom_embed = (const float*)d_in[3];
    const float* ip_W0 = (const float*)d_in[4];
    const float* ip_b0 = (const float*)d_in[5];
    const float* ip_W1 = (const float*)d_in[6];
    const float* ip_b1 = (const float*)d_in[7];
    const float* ly_W0 = (const float*)d_in[8];
    const float* ly_b0 = (const float*)d_in[9];
    const float* ly_W1 = (const float*)d_in[10];
    const float* ly_b1 = (const float*)d_in[11];
    const float* ly_Ws = (const float*)d_in[12];
    const float* ly_Wv = (const float*)d_in[13];
    const float* et_W0 = (const float*)d_in[14];
    const float* et_b0 = (const float*)d_in[15];
    const float* et_W1 = (const float*)d_in[16];
    const float* et_b1 = (const float*)d_in[17];
    const float* no_W1 = (const float*)d_in[18];
    const float* no_W2 = (const float*)d_in[19];
    float* out = (float*)d_out;

    int N = in_sizes[0] / 3;   // 5000
    int E = in_sizes[2] / 2;   // 40000

    const int LY_SMEM = (32768 + 4096) * (int)sizeof(float);  // 147456 B
    cudaFuncSetAttribute(k_ly, cudaFuncAttributeMaxDynamicSharedMemorySize, LY_SMEM);

    k_zero<<<256, 256>>>(N);
    k_pretype<<<100, 32>>>(atom_embed, ip_W1, ip_b1);
    k_edge1<<<(E + 7) / 8, 256>>>(coords, atom_types, ei,
                                  ip_W0, ip_b0, ly_W0, ly_b0, et_W0, et_b0, E);
    k_norm1<<<(N * 32 + 255) / 256, 256>>>(N);
    k_ly<<<152, 256, LY_SMEM>>>(ly_W1, ly_b1, ei, E);
    k_norm2<<<(N + 7) / 8, 256>>>(ly_Ws, ly_Wv, N);
    k_et<<<(E + 7) / 8, 256>>>(et_W1, et_b1, ei, out, E);
    k_nodeout<<<(N + 127) / 128, 128>>>(no_W1, no_W2, out + (size_t)E * 5, N);
}

// round 2
// speedup vs baseline: 1.5701x; 1.5701x over previous
#include <cuda_runtime.h>
#include <math.h>

#define NN 5000
#define EE 40000

// ---------------- scratch (device globals: no allocations allowed) ----------
__device__ float g_sh1[EE * 3];   // sqrt3 * (ny, nz, nx)
__device__ float g_hly[EE * 8];   // hidden activations of ly MLP
__device__ float g_het[EE * 8];   // hidden activations of et MLP
__device__ float g_s [NN * 32];   // stage-1 node scalars (accum then mean)
__device__ float g_v [NN * 96];   // stage-1 node vectors [u*3+i]
__device__ float g_cs[NN * 32];   // layer conv scalar accum
__device__ float g_cv[NN * 96];   // layer conv vector accum
__device__ float g_s2[NN * 32];   // final node scalars
__device__ float g_v2[NN * 96];   // final node vectors
__device__ float g_cnt[NN];       // in-degree
__device__ float g_A1[100 * 9 * 32]; // per-type: sum_u emb[t,u]*ipW1[k, u*32+w] (+bias k=8)
__device__ float g_A2[100 * 9 * 32]; // same for the 1o path (offset 1024)
// per-node precontracted ly weights:
// G[node][k=0..8][8 rows][32 w], rows per k: {Y0, Y1, Z2_0, Z2_1} {Z2_2, Z3_0, Z3_1, Z3_2}
__device__ float g_G[NN * 2304];

#define FULLMASK 0xffffffffu
__device__ __forceinline__ float siluf(float x) { return x / (1.f + __expf(-x)); }

constexpr float SQRT3      = 1.7320508075688772f;
constexpr float INV_SQRT3  = 0.57735026918962576f;
constexpr float C_IP       = 0.17677669529663687f;  // 1/sqrt(32)
constexpr float C_LY       = 0.125f;                // 1/sqrt(64)
constexpr float C_ET       = 0.08838834764831843f;  // 1/sqrt(128)
constexpr float LC         = 0.17677669529663687f;  // o3.Linear norm 1/sqrt(32)
constexpr float INV_SQRT32 = 0.17677669529663687f;
constexpr float INV_SQRT13 = 0.27735009811261457f;
constexpr float CUTOFF     = 5.0f;

// ---------------- kernels ----------------------------------------------------

__global__ void k_zero(int N) {
    int tid = blockIdx.x * blockDim.x + threadIdx.x;
    int stride = gridDim.x * blockDim.x;
    for (int i = tid; i < N * 32; i += stride) { g_s[i] = 0.f; g_cs[i] = 0.f; }
    for (int i = tid; i < N * 96; i += stride) { g_v[i] = 0.f; g_cv[i] = 0.f; }
    for (int i = tid; i < N;      i += stride) g_cnt[i] = 0.f;
}

// per-atom-type contraction of atom_embed with ip_W1 / ip_b1
__global__ void k_pretype(const float* __restrict__ emb,
                          const float* __restrict__ ipW1,
                          const float* __restrict__ ipb1) {
    int t = blockIdx.x;        // 0..99
    int w = threadIdx.x;       // 0..31
    float e[32];
#pragma unroll
    for (int u = 0; u < 32; u++) e[u] = emb[t * 32 + u];
    for (int k = 0; k < 8; k++) {
        float a1 = 0.f, a2 = 0.f;
#pragma unroll
        for (int u = 0; u < 32; u++) {
            a1 += e[u] * ipW1[k * 2048 +        u * 32 + w];
            a2 += e[u] * ipW1[k * 2048 + 1024 + u * 32 + w];
        }
        g_A1[t * 288 + k * 32 + w] = a1;
        g_A2[t * 288 + k * 32 + w] = a2;
    }
    float b1 = 0.f, b2 = 0.f;
#pragma unroll
    for (int u = 0; u < 32; u++) {
        b1 += e[u] * ipb1[       u * 32 + w];
        b2 += e[u] * ipb1[1024 + u * 32 + w];
    }
    g_A1[t * 288 + 8 * 32 + w] = b1;
    g_A2[t * 288 + 8 * 32 + w] = b2;
}

// per-edge geometry + 3 radial-MLP hiddens + stage-1 message & scatter
__global__ void k_edge1(const float* __restrict__ coords,
                        const int*   __restrict__ atom_types,
                        const int*   __restrict__ ei,
                        const float* __restrict__ ipW0, const float* __restrict__ ipb0,
                        const float* __restrict__ lyW0, const float* __restrict__ lyb0,
                        const float* __restrict__ etW0, const float* __restrict__ etb0,
                        int E) {
    int lane = threadIdx.x & 31;
    int e = blockIdx.x * (blockDim.x >> 5) + (threadIdx.x >> 5);
    if (e >= E) return;
    int src = ei[e], dst = ei[E + e];

    float dx = coords[dst * 3 + 0] - coords[src * 3 + 0];
    float dy = coords[dst * 3 + 1] - coords[src * 3 + 1];
    float dz = coords[dst * 3 + 2] - coords[src * 3 + 2];
    float d  = sqrtf(dx * dx + dy * dy + dz * dz + 1e-12f);
    float inv_d = 1.f / d;
    float nx = dx * inv_d, ny = dy * inv_d, nz = dz * inv_d;
    float sh_0 = SQRT3 * ny, sh_1 = SQRT3 * nz, sh_2 = SQRT3 * nx;

    // gaussian radial basis
    float attr[8];
    constexpr float STEP = CUTOFF / 9.0f;
    constexpr float INV_STEP = 9.0f / CUTOFF;
#pragma unroll
    for (int i = 0; i < 8; i++) {
        float diff = (d - (float)(i + 1) * STEP) * INV_STEP;
        attr[i] = __expf(-diff * diff) * (1.0f / 1.12f);
    }

    // lanes 0..7 -> ip hidden, 8..15 -> ly hidden, 16..23 -> et hidden
    int grp = lane >> 3;
    int j   = lane & 7;
    const float* W0 = (grp == 1) ? lyW0 : (grp == 2) ? etW0 : ipW0;
    const float* b0 = (grp == 1) ? lyb0 : (grp == 2) ? etb0 : ipb0;
    float pre = b0[j];
#pragma unroll
    for (int i = 0; i < 8; i++) pre += attr[i] * W0[i * 8 + j];
    float myh = siluf(pre);

    if (grp == 1) g_hly[e * 8 + j] = myh;
    if (grp == 2) g_het[e * 8 + j] = myh;
    if (lane < 3) g_sh1[e * 3 + lane] = (lane == 0) ? sh_0 : (lane == 1) ? sh_1 : sh_2;

    // stage-1 message via per-type precomputed matrices
    int t = atom_types[src];
    const float* A1 = &g_A1[t * 288];
    const float* A2 = &g_A2[t * 288];
    float m1 = A1[8 * 32 + lane];
    float m2 = A2[8 * 32 + lane];
#pragma unroll
    for (int k = 0; k < 8; k++) {
        float hk = __shfl_sync(FULLMASK, myh, k);  // lanes 0..7 hold ip hidden
        m1 += hk * A1[k * 32 + lane];
        m2 += hk * A2[k * 32 + lane];
    }
    atomicAdd(&g_s[dst * 32 + lane], C_IP * m1);
    float cm2 = C_IP * m2;
    atomicAdd(&g_v[dst * 96 + lane * 3 + 0], cm2 * sh_0);
    atomicAdd(&g_v[dst * 96 + lane * 3 + 1], cm2 * sh_1);
    atomicAdd(&g_v[dst * 96 + lane * 3 + 2], cm2 * sh_2);
    if (lane == 0) atomicAdd(&g_cnt[dst], 1.f);
}

// divide stage-1 accumulators by count (scatter mean)
__global__ void k_norm1(int N) {
    int idx = blockIdx.x * blockDim.x + threadIdx.x;
    if (idx >= N * 32) return;
    int n = idx >> 5;
    float c = g_cnt[n];
    float inv = 1.f / fmaxf(c, 1.f);
    g_s[idx] *= inv;
    int u = idx & 31;
    g_v[n * 96 + u * 3 + 0] *= inv;
    g_v[n * 96 + u * 3 + 1] *= inv;
    g_v[n * 96 + u * 3 + 2] *= inv;
}

// ---------- NEW: per-node precontraction of ly weights ------------------------
// For each node n, each k (0..8, k=8 = bias), each output channel w:
//   Y0 = sum_u s[n,u]   * W[k,0,u,w]
//   Y1 = sum_u s[n,u]   * W[k,1,u,w]
//   Z2_i = sum_u v[n,u,i] * W[k,2,u,w]
//   Z3_i = sum_u v[n,u,i] * W[k,3,u,w]
// stored as two float4s per (n,k,w): {Y0,Y1,Z2_0,Z2_1}, {Z2_2,Z3_0,Z3_1,Z3_2}
__global__ void __launch_bounds__(256)
k_pre_ly(const float* __restrict__ W1, const float* __restrict__ B1, int N) {
    __shared__ float s_sm[32][32];
    __shared__ float v_sm[32][96];
    int tid = threadIdx.x;
    int w = tid & 31;
    int q = tid >> 5;            // node subgroup 0..7 (4 nodes each)
    int nb = blockIdx.x * 32;    // 32 nodes per block

    // stage node features
    for (int i = tid; i < 32 * 32; i += 256) {
        int n = nb + (i >> 5);
        s_sm[i >> 5][i & 31] = (n < N) ? g_s[n * 32 + (i & 31)] : 0.f;
    }
    for (int i = tid; i < 32 * 96; i += 256) {
        int n = nb + (i / 96);
        v_sm[i / 96][i % 96] = (n < N) ? g_v[n * 96 + (i % 96)] : 0.f;
    }
    __syncthreads();

    int n0 = q * 4;  // local node base for this thread group

    for (int k = 0; k < 9; k++) {
        const float* Wk = (k < 8) ? (W1 + k * 4096) : B1;
        float y0[4] = {0.f, 0.f, 0.f, 0.f};
        float y1[4] = {0.f, 0.f, 0.f, 0.f};
        float z2[4][3] = {};
        float z3[4][3] = {};
#pragma unroll 4
        for (int u = 0; u < 32; u++) {
            float w0 = Wk[           u * 32 + w];
            float w1 = Wk[1024 +     u * 32 + w];
            float w2 = Wk[2048 +     u * 32 + w];
            float w3 = Wk[3072 +     u * 32 + w];
#pragma unroll
            for (int nn = 0; nn < 4; nn++) {
                float su = s_sm[n0 + nn][u];
                float v0 = v_sm[n0 + nn][u * 3 + 0];
                float v1 = v_sm[n0 + nn][u * 3 + 1];
                float v2 = v_sm[n0 + nn][u * 3 + 2];
                y0[nn] += su * w0;
                y1[nn] += su * w1;
                z2[nn][0] += v0 * w2;  z2[nn][1] += v1 * w2;  z2[nn][2] += v2 * w2;
                z3[nn][0] += v0 * w3;  z3[nn][1] += v1 * w3;  z3[nn][2] += v2 * w3;
            }
        }
#pragma unroll
        for (int nn = 0; nn < 4; nn++) {
            int n = nb + n0 + nn;
            if (n < N) {
                float4* Gp = reinterpret_cast<float4*>(&g_G[n * 2304]);
                Gp[(2 * k + 0) * 32 + w] = make_float4(y0[nn], y1[nn], z2[nn][0], z2[nn][1]);
                Gp[(2 * k + 1) * 32 + w] = make_float4(z2[nn][2], z3[nn][0], z3[nn][1], z3[nn][2]);
            }
        }
    }
}

// ---------- NEW: per-edge apply of precontracted weights ----------------------
__global__ void __launch_bounds__(256)
k_apply_ly(const int* __restrict__ ei, int E) {
    int lane = threadIdx.x & 31;
    int e = blockIdx.x * (blockDim.x >> 5) + (threadIdx.x >> 5);
    if (e >= E) return;
    int src = ei[e], dst = ei[E + e];

    float sh_0 = g_sh1[e * 3 + 0], sh_1 = g_sh1[e * 3 + 1], sh_2 = g_sh1[e * 3 + 2];
    const float4* hp = reinterpret_cast<const float4*>(&g_hly[e * 8]);
    float4 ha = hp[0], hb = hp[1];
    float h[9] = {ha.x, ha.y, ha.z, ha.w, hb.x, hb.y, hb.z, hb.w, 1.0f};

    const float4* Gp = reinterpret_cast<const float4*>(&g_G[src * 2304]);
    float ys = 0.f, yv = 0.f;
    float z20 = 0.f, z21 = 0.f, z22 = 0.f;
    float z30 = 0.f, z31 = 0.f, z32 = 0.f;
#pragma unroll
    for (int k = 0; k < 9; k++) {
        float4 a = Gp[(2 * k + 0) * 32 + lane];
        float4 b = Gp[(2 * k + 1) * 32 + lane];
        float hk = h[k];
        ys  += hk * a.x;  yv  += hk * a.y;
        z20 += hk * a.z;  z21 += hk * a.w;
        z22 += hk * b.x;
        z30 += hk * b.y;  z31 += hk * b.z;  z32 += hk * b.w;
    }
    float out_s = ys + INV_SQRT3 * (sh_0 * z30 + sh_1 * z31 + sh_2 * z32);
    atomicAdd(&g_cs[dst * 32 + lane],         C_LY * out_s);
    atomicAdd(&g_cv[dst * 96 + lane * 3 + 0], C_LY * (sh_0 * yv + z20));
    atomicAdd(&g_cv[dst * 96 + lane * 3 + 1], C_LY * (sh_1 * yv + z21));
    atomicAdd(&g_cv[dst * 96 + lane * 3 + 2], C_LY * (sh_2 * yv + z22));
}

// conv mean + linear self-interaction -> final node features
__global__ void k_norm2(const float* __restrict__ Ws, const float* __restrict__ Wv, int N) {
    int lane = threadIdx.x & 31;
    int n = blockIdx.x * (blockDim.x >> 5) + (threadIdx.x >> 5);
    if (n >= N) return;
    float inv = 1.f / fmaxf(g_cnt[n], 1.f);
    float sl  = g_s[n * 32 + lane];
    float vl0 = g_v[n * 96 + lane * 3 + 0];
    float vl1 = g_v[n * 96 + lane * 3 + 1];
    float vl2 = g_v[n * 96 + lane * 3 + 2];
    float ls = 0.f, lv0 = 0.f, lv1 = 0.f, lv2 = 0.f;
#pragma unroll 4
    for (int u = 0; u < 32; u++) {
        float su  = __shfl_sync(FULLMASK, sl,  u);
        float vu0 = __shfl_sync(FULLMASK, vl0, u);
        float vu1 = __shfl_sync(FULLMASK, vl1, u);
        float vu2 = __shfl_sync(FULLMASK, vl2, u);
        float ws = Ws[u * 32 + lane];
        float wv = Wv[u * 32 + lane];
        ls  += su  * ws;
        lv0 += vu0 * wv;
        lv1 += vu1 * wv;
        lv2 += vu2 * wv;
    }
    g_s2[n * 32 + lane]         = g_cs[n * 32 + lane] * inv         + LC * ls;
    g_v2[n * 96 + lane * 3 + 0] = g_cv[n * 96 + lane * 3 + 0] * inv + LC * lv0;
    g_v2[n * 96 + lane * 3 + 1] = g_cv[n * 96 + lane * 3 + 1] * inv + LC * lv1;
    g_v2[n * 96 + lane * 3 + 2] = g_cv[n * 96 + lane * 3 + 2] * inv + LC * lv2;
}

// edge output tensor product -> 5 bond logits per edge
__global__ void k_et(const float* __restrict__ W1, const float* __restrict__ B1,
                     const int* __restrict__ ei, float* __restrict__ out, int E) {
    __shared__ float sW[8 * 640];
    __shared__ float sB[640];
    for (int i = threadIdx.x; i < 8 * 640; i += blockDim.x) sW[i] = W1[i];
    for (int i = threadIdx.x; i < 640;     i += blockDim.x) sB[i] = B1[i];
    __syncthreads();

    int lane = threadIdx.x & 31;   // = u
    int e = blockIdx.x * (blockDim.x >> 5) + (threadIdx.x >> 5);
    if (e >= E) return;
    int src = ei[e], dst = ei[E + e];
    float sh_0 = g_sh1[e * 3 + 0], sh_1 = g_sh1[e * 3 + 1], sh_2 = g_sh1[e * 3 + 2];
    const float4* hp = reinterpret_cast<const float4*>(&g_het[e * 8]);
    float4 ha = hp[0], hb = hp[1];
    float h[8] = {ha.x, ha.y, ha.z, ha.w, hb.x, hb.y, hb.z, hb.w};

    float x[4];
    x[0] = g_s2[src * 32 + lane];
    {
        float a = g_v2[src * 96 + lane * 3 + 0];
        float b = g_v2[src * 96 + lane * 3 + 1];
        float c = g_v2[src * 96 + lane * 3 + 2];
        x[1] = (a * sh_0 + b * sh_1 + c * sh_2) * INV_SQRT3;
    }
    x[2] = g_s2[dst * 32 + lane];
    {
        float a = g_v2[dst * 96 + lane * 3 + 0];
        float b = g_v2[dst * 96 + lane * 3 + 1];
        float c = g_v2[dst * 96 + lane * 3 + 2];
        x[3] = (a * sh_0 + b * sh_1 + c * sh_2) * INV_SQRT3;
    }

    float p0 = 0.f, p1 = 0.f, p2 = 0.f, p3 = 0.f, p4 = 0.f;
#pragma unroll
    for (int P = 0; P < 4; P++) {
        int base = P * 160 + lane * 5;
        float xp = x[P];
#pragma unroll
        for (int w = 0; w < 5; w++) {
            float wt = sB[base + w];
#pragma unroll
            for (int k = 0; k < 8; k++) wt += h[k] * sW[k * 640 + base + w];
            float contrib = xp * wt;
            if (w == 0) p0 += contrib;
            else if (w == 1) p1 += contrib;
            else if (w == 2) p2 += contrib;
            else if (w == 3) p3 += contrib;
            else p4 += contrib;
        }
    }
#pragma unroll
    for (int off = 16; off > 0; off >>= 1) {
        p0 += __shfl_xor_sync(FULLMASK, p0, off);
        p1 += __shfl_xor_sync(FULLMASK, p1, off);
        p2 += __shfl_xor_sync(FULLMASK, p2, off);
        p3 += __shfl_xor_sync(FULLMASK, p3, off);
        p4 += __shfl_xor_sync(FULLMASK, p4, off);
    }
    if (lane == 0) {
        out[e * 5 + 0] = C_ET * p0;
        out[e * 5 + 1] = C_ET * p1;
        out[e * 5 + 2] = C_ET * p2;
        out[e * 5 + 3] = C_ET * p3;
        out[e * 5 + 4] = C_ET * p4;
    }
}

// node output MLP (13x0e)
__global__ void k_nodeout(const float* __restrict__ W1, const float* __restrict__ W2,
                          float* __restrict__ out, int N) {
    int n = blockIdx.x * blockDim.x + threadIdx.x;
    if (n >= N) return;
    float s[32];
#pragma unroll
    for (int u = 0; u < 32; u++) s[u] = g_s2[n * 32 + u];
    float h[13];
#pragma unroll
    for (int j = 0; j < 13; j++) {
        float pre = 0.f;
#pragma unroll
        for (int u = 0; u < 32; u++) pre += s[u] * W1[u * 13 + j];
        pre *= INV_SQRT32;
        h[j] = siluf(pre);
    }
#pragma unroll
    for (int j2 = 0; j2 < 13; j2++) {
        float o = 0.f;
#pragma unroll
        for (int j = 0; j < 13; j++) o += h[j] * W2[j * 13 + j2];
        out[n * 13 + j2] = o * INV_SQRT13;
    }
}

// ---------------- launch ------------------------------------------------------

extern "C" void kernel_launch(void* const* d_in, const int* in_sizes, int n_in,
                              void* d_out, int out_size) {
    const float* coords     = (const float*)d_in[0];
    const int*   atom_types = (const int*)  d_in[1];
    const int*   ei         = (const int*)  d_in[2];
    const float* atom_embed = (const float*)d_in[3];
    const float* ip_W0 = (const float*)d_in[4];
    const float* ip_b0 = (const float*)d_in[5];
    const float* ip_W1 = (const float*)d_in[6];
    const float* ip_b1 = (const float*)d_in[7];
    const float* ly_W0 = (const float*)d_in[8];
    const float* ly_b0 = (const float*)d_in[9];
    const float* ly_W1 = (const float*)d_in[10];
    const float* ly_b1 = (const float*)d_in[11];
    const float* ly_Ws = (const float*)d_in[12];
    const float* ly_Wv = (const float*)d_in[13];
    const float* et_W0 = (const float*)d_in[14];
    const float* et_b0 = (const float*)d_in[15];
    const float* et_W1 = (const float*)d_in[16];
    const float* et_b1 = (const float*)d_in[17];
    const float* no_W1 = (const float*)d_in[18];
    const float* no_W2 = (const float*)d_in[19];
    float* out = (float*)d_out;

    int N = in_sizes[0] / 3;   // 5000
    int E = in_sizes[2] / 2;   // 40000

    k_zero<<<256, 256>>>(N);
    k_pretype<<<100, 32>>>(atom_embed, ip_W1, ip_b1);
    k_edge1<<<(E + 7) / 8, 256>>>(coords, atom_types, ei,
                                  ip_W0, ip_b0, ly_W0, ly_b0, et_W0, et_b0, E);
    k_norm1<<<(N * 32 + 255) / 256, 256>>>(N);
    k_pre_ly<<<(N + 31) / 32, 256>>>(ly_W1, ly_b1, N);
    k_apply_ly<<<(E + 7) / 8, 256>>>(ei, E);
    k_norm2<<<(N + 7) / 8, 256>>>(ly_Ws, ly_Wv, N);
    k_et<<<(E + 7) / 8, 256>>>(et_W1, et_b1, ei, out, E);
    k_nodeout<<<(N + 127) / 128, 128>>>(no_W1, no_W2, out + (size_t)E * 5, N);
}